// round 2
// baseline (speedup 1.0000x reference)
#include <cuda_runtime.h>
#include <math.h>

#define NN 6144
#define HID 48
#define NHEADS 3
#define DHEAD 16
#define MAXNZ 832
#define QKV_ROWS 32

static __device__ float g_q[NN * HID];
static __device__ float g_k[NHEADS * NN * DHEAD];
static __device__ float g_v[NHEADS * NN * DHEAD];
static __device__ float g_vsum[HID];

// ---------------- QKV projection: q = h @ Wq^T + bq, etc. ----------------
__global__ __launch_bounds__(256) void qkv_kernel(
    const float* __restrict__ h,
    const float* __restrict__ Wq, const float* __restrict__ bq,
    const float* __restrict__ Wk, const float* __restrict__ bk,
    const float* __restrict__ Wv, const float* __restrict__ bv)
{
    __shared__ float sWT[3 * HID * HID];  // [m][c][o] transposed
    __shared__ float sh[QKV_ROWS * HID];
    __shared__ float sb[3 * HID];
    const int tid = threadIdx.x;
    const int i0 = blockIdx.x * QKV_ROWS;

    for (int t = tid; t < 3 * HID * HID; t += 256) {
        int m = t / (HID * HID);
        int idx = t - m * (HID * HID);
        int o = idx / HID, c = idx - o * HID;
        const float* W = (m == 0) ? Wq : ((m == 1) ? Wk : Wv);
        sWT[(m * HID + c) * HID + o] = W[o * HID + c];
    }
    if (tid < 3 * HID) {
        const float* bs = (tid < HID) ? bq : (tid < 2 * HID ? bk : bv);
        sb[tid] = bs[tid % HID];
    }
    for (int t = tid; t < QKV_ROWS * HID; t += 256)
        sh[t] = h[(size_t)i0 * HID + t];
    __syncthreads();

    for (int t = tid; t < QKV_ROWS * 3 * HID; t += 256) {
        int r = t / (3 * HID);
        int rem = t - r * (3 * HID);
        int m = rem / HID;
        int o = rem - m * HID;
        float acc = sb[m * HID + o];
        const float* w = &sWT[m * HID * HID];
        const float* hr = &sh[r * HID];
#pragma unroll
        for (int c = 0; c < HID; c++)
            acc = fmaf(hr[c], w[c * HID + o], acc);
        int i = i0 + r;
        if (m == 0) {
            g_q[i * HID + o] = acc;
        } else {
            int hd = o / DHEAD, d = o - hd * DHEAD;
            float* dst = (m == 1) ? g_k : g_v;
            dst[((size_t)hd * NN + i) * DHEAD + d] = acc;
        }
    }
}

// ---------------- Per-head column sum of V ----------------
__global__ void vsum_kernel()
{
    const int hd = blockIdx.x / DHEAD, d = blockIdx.x % DHEAD;
    const int tid = threadIdx.x;
    float s = 0.f;
    for (int j = tid; j < NN; j += 128)
        s += g_v[((size_t)hd * NN + j) * DHEAD + d];
    for (int o = 16; o; o >>= 1) s += __shfl_xor_sync(0xffffffffu, s, o);
    __shared__ float red[4];
    if ((tid & 31) == 0) red[tid >> 5] = s;
    __syncthreads();
    if (tid == 0) g_vsum[blockIdx.x] = red[0] + red[1] + red[2] + red[3];
}

// ---------------- Main attention: one block per row, all 3 heads ----------------
__global__ __launch_bounds__(256) void attn_kernel(
    const float* __restrict__ A, float* __restrict__ out, float* __restrict__ scores)
{
    const int i = blockIdx.x;
    const int tid = threadIdx.x;
    const int lane = tid & 31;
    const int warp = tid >> 5;
    const unsigned FULL = 0xffffffffu;

    __shared__ float s_row[NN];          // 24576 B: composed output row
    __shared__ int   s_idx[MAXNZ];
    __shared__ float s_aval[MAXNZ];      // A values at nonzeros
    __shared__ float s_val[MAXNZ];       // score -> exp(score-m)
    __shared__ float s_red[8][DHEAD];
    __shared__ float s_scalar[8];
    __shared__ int   s_cnt;
    __shared__ float s_m, s_l;

    if (tid == 0) s_cnt = 0;
    __syncthreads();

    // ---- Phase 1 (once): load A row, compact nonzeros (ballot-free warp scan) ----
    const float4* arow = reinterpret_cast<const float4*>(A + (size_t)i * NN);
    for (int b = tid; b < NN / 4; b += 256) {   // exactly 6 uniform iterations
        float4 a = arow[b];
        float av[4] = {a.x, a.y, a.z, a.w};
        int nz[4];
        int cnt4 = 0;
#pragma unroll
        for (int c = 0; c < 4; c++) { nz[c] = (av[c] != 0.0f); cnt4 += nz[c]; }
        int scan = cnt4;
#pragma unroll
        for (int o = 1; o < 32; o <<= 1) {
            int t = __shfl_up_sync(FULL, scan, o);
            if (lane >= o) scan += t;
        }
        int total = __shfl_sync(FULL, scan, 31);
        int base = 0;
        if (lane == 31 && total > 0) base = atomicAdd(&s_cnt, total);
        base = __shfl_sync(FULL, base, 31);
        int pos = base + scan - cnt4;
#pragma unroll
        for (int c = 0; c < 4; c++) {
            if (nz[c]) {
                if (pos < MAXNZ) { s_idx[pos] = b * 4 + c; s_aval[pos] = av[c]; }
                pos++;
            }
        }
    }
    __syncthreads();
    const int nnz = min(s_cnt, MAXNZ);
    const float scale = sqrtf((float)NN);

    for (int hd = 0; hd < NHEADS; hd++) {
        // q row into registers (broadcast load, L2/L1 hit)
        float qr[DHEAD];
#pragma unroll
        for (int d = 0; d < DHEAD; d++) qr[d] = __ldg(&g_q[i * HID + hd * DHEAD + d]);

        // ---- Phase 2: dots at nonzeros + row max (zeros contribute score 0) ----
        const float4* kh = reinterpret_cast<const float4*>(g_k + (size_t)hd * NN * DHEAD);
        float lmax = 0.0f;
        for (int t = tid; t < nnz; t += 256) {
            int j = s_idx[t];
            float4 k0 = kh[j * 4 + 0], k1 = kh[j * 4 + 1], k2 = kh[j * 4 + 2], k3 = kh[j * 4 + 3];
            float dot = qr[0] * k0.x;
            dot = fmaf(qr[1], k0.y, dot);  dot = fmaf(qr[2], k0.z, dot);  dot = fmaf(qr[3], k0.w, dot);
            dot = fmaf(qr[4], k1.x, dot);  dot = fmaf(qr[5], k1.y, dot);  dot = fmaf(qr[6], k1.z, dot);
            dot = fmaf(qr[7], k1.w, dot);  dot = fmaf(qr[8], k2.x, dot);  dot = fmaf(qr[9], k2.y, dot);
            dot = fmaf(qr[10], k2.z, dot); dot = fmaf(qr[11], k2.w, dot); dot = fmaf(qr[12], k3.x, dot);
            dot = fmaf(qr[13], k3.y, dot); dot = fmaf(qr[14], k3.z, dot); dot = fmaf(qr[15], k3.w, dot);
            float s = s_aval[t] * dot * scale;
            s_val[t] = s;
            lmax = fmaxf(lmax, s);
        }
#pragma unroll
        for (int o = 16; o; o >>= 1) lmax = fmaxf(lmax, __shfl_xor_sync(FULL, lmax, o));
        if (lane == 0) s_scalar[warp] = lmax;
        __syncthreads();
        if (tid == 0) {
            float m = 0.0f;
            for (int w = 0; w < 8; w++) m = fmaxf(m, s_scalar[w]);
            s_m = m;
        }
        __syncthreads();
        const float m = s_m;
        const float ze = expf(-m);  // exp(score-m) at every zero entry

        // ---- Phase 3: exp + sum + out accumulation ----
        const float4* vh = reinterpret_cast<const float4*>(g_v + (size_t)hd * NN * DHEAD);
        float lsum = 0.f;
        float acc[DHEAD];
#pragma unroll
        for (int d = 0; d < DHEAD; d++) acc[d] = 0.f;
        for (int t = tid; t < nnz; t += 256) {
            float e = expf(s_val[t] - m);
            s_val[t] = e;
            lsum += e;
            float w = e - ze;  // out = sum_nz (e-ze)*v/l + z*Vsum
            int j = s_idx[t];
            float4 v0 = vh[j * 4 + 0], v1 = vh[j * 4 + 1], v2 = vh[j * 4 + 2], v3 = vh[j * 4 + 3];
            acc[0]  = fmaf(w, v0.x, acc[0]);  acc[1]  = fmaf(w, v0.y, acc[1]);
            acc[2]  = fmaf(w, v0.z, acc[2]);  acc[3]  = fmaf(w, v0.w, acc[3]);
            acc[4]  = fmaf(w, v1.x, acc[4]);  acc[5]  = fmaf(w, v1.y, acc[5]);
            acc[6]  = fmaf(w, v1.z, acc[6]);  acc[7]  = fmaf(w, v1.w, acc[7]);
            acc[8]  = fmaf(w, v2.x, acc[8]);  acc[9]  = fmaf(w, v2.y, acc[9]);
            acc[10] = fmaf(w, v2.z, acc[10]); acc[11] = fmaf(w, v2.w, acc[11]);
            acc[12] = fmaf(w, v3.x, acc[12]); acc[13] = fmaf(w, v3.y, acc[13]);
            acc[14] = fmaf(w, v3.z, acc[14]); acc[15] = fmaf(w, v3.w, acc[15]);
        }
#pragma unroll
        for (int o = 16; o; o >>= 1) lsum += __shfl_xor_sync(FULL, lsum, o);
#pragma unroll
        for (int d = 0; d < DHEAD; d++) {
            float x = acc[d];
#pragma unroll
            for (int o = 16; o; o >>= 1) x += __shfl_xor_sync(FULL, x, o);
            acc[d] = x;
        }
        if (lane == 0) {
            s_scalar[warp] = lsum;
#pragma unroll
            for (int d = 0; d < DHEAD; d++) s_red[warp][d] = acc[d];
        }
        __syncthreads();
        if (tid == 0) {
            float l = (float)(NN - nnz) * ze;
            for (int w = 0; w < 8; w++) l += s_scalar[w];
            s_l = l;
        }
        __syncthreads();
        const float l = s_l;
        const float inv_l = 1.0f / l;
        const float z = ze * inv_l;

        if (tid < DHEAD) {
            float s = 0.f;
            for (int w = 0; w < 8; w++) s += s_red[w][tid];
            out[(size_t)i * HID + hd * DHEAD + tid] = s * inv_l + z * g_vsum[hd * DHEAD + tid];
        }

        // ---- Phase 4: compose row in SMEM, coalesced write to scores ----
        float4 zf = make_float4(z, z, z, z);
        float4* rowv = reinterpret_cast<float4*>(s_row);
        for (int b = tid; b < NN / 4; b += 256) rowv[b] = zf;
        __syncthreads();
        for (int t = tid; t < nnz; t += 256) s_row[s_idx[t]] = s_val[t] * inv_l;
        __syncthreads();
        float4* dst = reinterpret_cast<float4*>(scores + ((size_t)hd * NN + i) * NN);
        for (int b = tid; b < NN / 4; b += 256) dst[b] = rowv[b];
        __syncthreads();   // protect s_row/s_val before next head reuses them
    }
}

extern "C" void kernel_launch(void* const* d_in, const int* in_sizes, int n_in,
                              void* d_out, int out_size)
{
    const float* A  = (const float*)d_in[0];
    const float* h  = (const float*)d_in[1];
    const float* Wq = (const float*)d_in[2];
    const float* bq = (const float*)d_in[3];
    const float* Wk = (const float*)d_in[4];
    const float* bk = (const float*)d_in[5];
    const float* Wv = (const float*)d_in[6];
    const float* bv = (const float*)d_in[7];
    float* out = (float*)d_out;
    float* scores = out + (size_t)NN * HID;

    qkv_kernel<<<NN / QKV_ROWS, 256>>>(h, Wq, bq, Wk, bk, Wv, bv);
    vsum_kernel<<<NHEADS * DHEAD, 128>>>();
    attn_kernel<<<NN, 256>>>(A, out, scores);
}

// round 3
// speedup vs baseline: 1.1357x; 1.1357x over previous
#include <cuda_runtime.h>
#include <math.h>

#define NN 6144
#define HID 48
#define NHEADS 3
#define DHEAD 16
#define MAXNZ 832
#define QKV_ROWS 8

static __device__ float g_q[NN * HID];
static __device__ float g_k[NHEADS * NN * DHEAD];
static __device__ float g_v[NHEADS * NN * DHEAD];
static __device__ float g_vsum[HID];

// ---------------- QKV projection: q = h @ Wq^T + bq, etc. ----------------
__global__ __launch_bounds__(256) void qkv_kernel(
    const float* __restrict__ h,
    const float* __restrict__ Wq, const float* __restrict__ bq,
    const float* __restrict__ Wk, const float* __restrict__ bk,
    const float* __restrict__ Wv, const float* __restrict__ bv)
{
    __shared__ float sWT[3 * HID * HID];  // [m][c][o] transposed for stride-1 o access
    __shared__ float sh[QKV_ROWS * HID];
    __shared__ float sb[3 * HID];
    const int tid = threadIdx.x;
    const int i0 = blockIdx.x * QKV_ROWS;

    for (int t = tid; t < 3 * HID * HID; t += 256) {
        int m = t / (HID * HID);
        int idx = t - m * (HID * HID);
        int o = idx / HID, c = idx - o * HID;
        const float* W = (m == 0) ? Wq : ((m == 1) ? Wk : Wv);
        sWT[(m * HID + c) * HID + o] = W[o * HID + c];
    }
    if (tid < 3 * HID) {
        const float* bs = (tid < HID) ? bq : (tid < 2 * HID ? bk : bv);
        sb[tid] = bs[tid % HID];
    }
    for (int t = tid; t < QKV_ROWS * HID; t += 256)
        sh[t] = h[(size_t)i0 * HID + t];
    __syncthreads();

    for (int t = tid; t < QKV_ROWS * 3 * HID; t += 256) {
        int r = t / (3 * HID);
        int rem = t - r * (3 * HID);
        int m = rem / HID;
        int o = rem - m * HID;
        float acc = sb[m * HID + o];
        const float* w = &sWT[m * HID * HID];
        const float* hr = &sh[r * HID];
#pragma unroll
        for (int c = 0; c < HID; c++)
            acc = fmaf(hr[c], w[c * HID + o], acc);
        int i = i0 + r;
        if (m == 0) {
            g_q[i * HID + o] = acc;
        } else {
            int hd = o / DHEAD, d = o - hd * DHEAD;
            float* dst = (m == 1) ? g_k : g_v;
            dst[((size_t)hd * NN + i) * DHEAD + d] = acc;
        }
    }
}

// ---------------- Per-head column sum of V ----------------
__global__ void vsum_kernel()
{
    const int hd = blockIdx.x / DHEAD, d = blockIdx.x % DHEAD;
    const int tid = threadIdx.x;
    float s = 0.f;
    for (int j = tid; j < NN; j += 128)
        s += g_v[((size_t)hd * NN + j) * DHEAD + d];
    for (int o = 16; o; o >>= 1) s += __shfl_xor_sync(0xffffffffu, s, o);
    __shared__ float red[4];
    if ((tid & 31) == 0) red[tid >> 5] = s;
    __syncthreads();
    if (tid == 0) g_vsum[blockIdx.x] = red[0] + red[1] + red[2] + red[3];
}

// ---------------- Main attention: one block per row, one WARP per head ----------------
__global__ __launch_bounds__(96) void attn_kernel(
    const float* __restrict__ A, float* __restrict__ out, float* __restrict__ scores)
{
    const int i = blockIdx.x;
    const int tid = threadIdx.x;
    const int lane = tid & 31;
    const int warp = tid >> 5;          // 0..2 == head id
    const unsigned FULL = 0xffffffffu;

    __shared__ int   s_idx[MAXNZ];
    __shared__ float s_aval[MAXNZ];
    __shared__ float s_sc[NHEADS][MAXNZ];   // per-head score -> exp buffer
    __shared__ int   s_cnt;

    if (tid == 0) s_cnt = 0;
    __syncthreads();

    // ---- Phase 1 (all 3 warps): load A row, compact nonzeros ----
    const float4* arow = reinterpret_cast<const float4*>(A + (size_t)i * NN);
    for (int b = tid; b < NN / 4; b += 96) {   // 16 uniform iterations
        float4 a = arow[b];
        float av[4] = {a.x, a.y, a.z, a.w};
        int nz[4];
        int cnt4 = 0;
#pragma unroll
        for (int c = 0; c < 4; c++) { nz[c] = (av[c] != 0.0f); cnt4 += nz[c]; }
        int scan = cnt4;
#pragma unroll
        for (int o = 1; o < 32; o <<= 1) {
            int t = __shfl_up_sync(FULL, scan, o);
            if (lane >= o) scan += t;
        }
        int total = __shfl_sync(FULL, scan, 31);
        int base = 0;
        if (lane == 31 && total > 0) base = atomicAdd(&s_cnt, total);
        base = __shfl_sync(FULL, base, 31);
        int pos = base + scan - cnt4;
#pragma unroll
        for (int c = 0; c < 4; c++) {
            if (nz[c]) {
                if (pos < MAXNZ) { s_idx[pos] = b * 4 + c; s_aval[pos] = av[c]; }
                pos++;
            }
        }
    }
    __syncthreads();
    const int nnz = min(s_cnt, MAXNZ);

    // ---- From here on: warp == head, NO block barriers ----
    const int hd = warp;
    const float scale = sqrtf((float)NN);
    float* schead = s_sc[hd];

    float qr[DHEAD];
#pragma unroll
    for (int d = 0; d < DHEAD; d++) qr[d] = __ldg(&g_q[i * HID + hd * DHEAD + d]);

    // Pass A: dots at nonzeros + running max (zero entries contribute score 0)
    const float4* kh = reinterpret_cast<const float4*>(g_k + (size_t)hd * NN * DHEAD);
    float lmax = 0.0f;
    for (int t = lane; t < nnz; t += 32) {
        int j = s_idx[t];
        float4 k0 = kh[j * 4 + 0], k1 = kh[j * 4 + 1], k2 = kh[j * 4 + 2], k3 = kh[j * 4 + 3];
        float dot = qr[0] * k0.x;
        dot = fmaf(qr[1], k0.y, dot);  dot = fmaf(qr[2], k0.z, dot);  dot = fmaf(qr[3], k0.w, dot);
        dot = fmaf(qr[4], k1.x, dot);  dot = fmaf(qr[5], k1.y, dot);  dot = fmaf(qr[6], k1.z, dot);
        dot = fmaf(qr[7], k1.w, dot);  dot = fmaf(qr[8], k2.x, dot);  dot = fmaf(qr[9], k2.y, dot);
        dot = fmaf(qr[10], k2.z, dot); dot = fmaf(qr[11], k2.w, dot); dot = fmaf(qr[12], k3.x, dot);
        dot = fmaf(qr[13], k3.y, dot); dot = fmaf(qr[14], k3.z, dot); dot = fmaf(qr[15], k3.w, dot);
        float s = s_aval[t] * dot * scale;
        schead[t] = s;
        lmax = fmaxf(lmax, s);
    }
#pragma unroll
    for (int o = 16; o; o >>= 1) lmax = fmaxf(lmax, __shfl_xor_sync(FULL, lmax, o));
    const float m = lmax;
    const float ze = __expf(-m);   // exp(score - m) at every zero entry

    // Pass B: exp + sum + V accumulate  (out = [sum_nz (e-ze) v]/l + z*Vsum)
    const float4* vh = reinterpret_cast<const float4*>(g_v + (size_t)hd * NN * DHEAD);
    float lsum = 0.f;
    float acc[DHEAD];
#pragma unroll
    for (int d = 0; d < DHEAD; d++) acc[d] = 0.f;
    for (int t = lane; t < nnz; t += 32) {
        float e = __expf(schead[t] - m);
        schead[t] = e;
        lsum += e;
        float w = e - ze;
        int j = s_idx[t];
        float4 v0 = vh[j * 4 + 0], v1 = vh[j * 4 + 1], v2 = vh[j * 4 + 2], v3 = vh[j * 4 + 3];
        acc[0]  = fmaf(w, v0.x, acc[0]);  acc[1]  = fmaf(w, v0.y, acc[1]);
        acc[2]  = fmaf(w, v0.z, acc[2]);  acc[3]  = fmaf(w, v0.w, acc[3]);
        acc[4]  = fmaf(w, v1.x, acc[4]);  acc[5]  = fmaf(w, v1.y, acc[5]);
        acc[6]  = fmaf(w, v1.z, acc[6]);  acc[7]  = fmaf(w, v1.w, acc[7]);
        acc[8]  = fmaf(w, v2.x, acc[8]);  acc[9]  = fmaf(w, v2.y, acc[9]);
        acc[10] = fmaf(w, v2.z, acc[10]); acc[11] = fmaf(w, v2.w, acc[11]);
        acc[12] = fmaf(w, v3.x, acc[12]); acc[13] = fmaf(w, v3.y, acc[13]);
        acc[14] = fmaf(w, v3.z, acc[14]); acc[15] = fmaf(w, v3.w, acc[15]);
    }
#pragma unroll
    for (int o = 16; o; o >>= 1) lsum += __shfl_xor_sync(FULL, lsum, o);
#pragma unroll
    for (int d = 0; d < DHEAD; d++) {
#pragma unroll
        for (int o = 16; o; o >>= 1) acc[d] += __shfl_xor_sync(FULL, acc[d], o);
    }
    const float l = (float)(NN - nnz) * ze + lsum;
    const float inv_l = 1.0f / l;
    const float z = ze * inv_l;

    if (lane == 0) {
#pragma unroll
        for (int d = 0; d < DHEAD; d++)
            out[(size_t)i * HID + hd * DHEAD + d] = acc[d] * inv_l + z * g_vsum[hd * DHEAD + d];
    }

    // Fill scores row with z directly in global, then scatter p at nonzeros.
    // __syncwarp orders the fill stores before the scatter stores (row stays
    // L2-resident so the scatter merges without extra DRAM traffic).
    float* row = scores + ((size_t)hd * NN + i) * NN;
    float4 zf = make_float4(z, z, z, z);
    float4* rowv = reinterpret_cast<float4*>(row);
    for (int b = lane; b < NN / 4; b += 32) rowv[b] = zf;
    __syncwarp();
    for (int t = lane; t < nnz; t += 32) row[s_idx[t]] = schead[t] * inv_l;
}

extern "C" void kernel_launch(void* const* d_in, const int* in_sizes, int n_in,
                              void* d_out, int out_size)
{
    const float* A  = (const float*)d_in[0];
    const float* h  = (const float*)d_in[1];
    const float* Wq = (const float*)d_in[2];
    const float* bq = (const float*)d_in[3];
    const float* Wk = (const float*)d_in[4];
    const float* bk = (const float*)d_in[5];
    const float* Wv = (const float*)d_in[6];
    const float* bv = (const float*)d_in[7];
    float* out = (float*)d_out;
    float* scores = out + (size_t)NN * HID;

    qkv_kernel<<<NN / QKV_ROWS, 256>>>(h, Wq, bq, Wk, bk, Wv, bv);
    vsum_kernel<<<NHEADS * DHEAD, 128>>>();
    attn_kernel<<<NN, 96>>>(A, out, scores);
}